// round 1
// baseline (speedup 1.0000x reference)
#include <cuda_runtime.h>
#include <math.h>

// Problem constants
#define S_ 8192
#define D_ 2048
#define H_ 64
#define E_ 64
#define L_ 64

// Scratch (static device globals — no allocation allowed)
#define NPART 64
__device__ float g_vpart[NPART][D_];   // partial weighted column sums of x
__device__ float g_gate[2];            // softmax gate weights g0, g1
__device__ int   g_idx[2];             // selected expert indices

// ---------------------------------------------------------------------------
// Kernel 1: v_partial[b][d] = sum over 128 rows of w_out[s] * x[s][d]
// 64 blocks x 128 rows each; thread t owns 8 contiguous columns.
// ---------------------------------------------------------------------------
__global__ void __launch_bounds__(256) k_colsum(const float* __restrict__ x,
                                                const float* __restrict__ wout) {
    __shared__ float ws[128];
    const int b = blockIdx.x;
    const int t = threadIdx.x;
    const int row0 = b * 128;
    if (t < 128) ws[t] = wout[row0 + t];
    __syncthreads();

    const int d0 = t * 8;
    float acc[8];
#pragma unroll
    for (int i = 0; i < 8; i++) acc[i] = 0.f;

    const float* xp = x + (size_t)row0 * D_ + d0;
#pragma unroll 4
    for (int r = 0; r < 128; r++) {
        const float w = ws[r];
        const float4 a = *(const float4*)(xp);
        const float4 c = *(const float4*)(xp + 4);
        acc[0] = fmaf(w, a.x, acc[0]);
        acc[1] = fmaf(w, a.y, acc[1]);
        acc[2] = fmaf(w, a.z, acc[2]);
        acc[3] = fmaf(w, a.w, acc[3]);
        acc[4] = fmaf(w, c.x, acc[4]);
        acc[5] = fmaf(w, c.y, acc[5]);
        acc[6] = fmaf(w, c.z, acc[6]);
        acc[7] = fmaf(w, c.w, acc[7]);
        xp += D_;
    }
#pragma unroll
    for (int i = 0; i < 8; i++) g_vpart[b][d0 + i] = acc[i];
}

// ---------------------------------------------------------------------------
// Kernel 2: finish the gate.
//   v = sum_b vpart[b]        (deterministic fixed-order reduction)
//   u = Wg_in @ v             (64 dots of length 2048, warp-parallel)
//   scores = Wg_lin @ u       (64 dots of length 64)
//   top-2 (jax tie-break: lower index first), softmax over the 2 values
// Single block, 256 threads.
// ---------------------------------------------------------------------------
__global__ void __launch_bounds__(256) k_gate(const float* __restrict__ Wg_in,
                                              const float* __restrict__ Wg_lin) {
    __shared__ float v[D_];
    __shared__ float u[H_];
    __shared__ float sc[E_];
    const int t = threadIdx.x;

    for (int d = t; d < D_; d += 256) {
        float s = 0.f;
#pragma unroll 8
        for (int b = 0; b < NPART; b++) s += g_vpart[b][d];
        v[d] = s;
    }
    __syncthreads();

    const int w = t >> 5, lane = t & 31;
    // 8 warps x 8 rows each -> all 64 rows of Wg_in
    for (int jj = 0; jj < 8; jj++) {
        const int j = w * 8 + jj;
        const float* wr = Wg_in + (size_t)j * D_;
        float s = 0.f;
#pragma unroll 8
        for (int d = lane; d < D_; d += 32) s = fmaf(wr[d], v[d], s);
#pragma unroll
        for (int off = 16; off; off >>= 1) s += __shfl_down_sync(0xffffffffu, s, off);
        if (lane == 0) u[j] = s;
    }
    __syncthreads();

    if (t < E_) {
        float s = 0.f;
#pragma unroll
        for (int j = 0; j < H_; j++) s = fmaf(Wg_lin[t * H_ + j], u[j], s);
        sc[t] = s;
    }
    __syncthreads();

    if (t == 0) {
        int i0 = 0;
        for (int e = 1; e < E_; e++) if (sc[e] > sc[i0]) i0 = e;
        int i1 = (i0 == 0) ? 1 : 0;
        for (int e = 0; e < E_; e++) {
            if (e == i0 || e == i1) continue;
            if (sc[e] > sc[i1]) i1 = e;
        }
        const float m = sc[i0];
        const float e0 = expf(sc[i0] - m);
        const float e1 = expf(sc[i1] - m);
        const float inv = 1.f / (e0 + e1);
        g_gate[0] = e0 * inv;
        g_gate[1] = e1 * inv;
        g_idx[0] = i0;
        g_idx[1] = i1;
    }
}

// ---------------------------------------------------------------------------
// Kernel 3: fused expert GEMM + normalize + GELU + weighted combine.
//   C[s, 0:64]   = x[s,:] . We[idx0]^T      C[s, 64:128] = x[s,:] . We[idx1]^T
//   out[s,l] = g0*gelu(C[s,l]/||C[s,0:64]||) + g1*gelu(C[s,64+l]/||C[s,64:128]||)
// Tile: 64 rows x 128 cols per CTA, 256 threads, 4x8 micro-tile, Kc=32,
// register-staged global prefetch to hide LDG latency.
// ---------------------------------------------------------------------------
__device__ __forceinline__ float gelu_exact(float x) {
    return 0.5f * x * (1.f + erff(x * 0.70710678118654752440f));
}

__global__ void __launch_bounds__(256) k_expert(const float* __restrict__ x,
                                                const float* __restrict__ We,
                                                float* __restrict__ out) {
    __shared__ union {
        struct { float A[32][64]; float B[32][128]; } s;  // 24 KB
        float C[64][128];                                  // 32 KB
    } sm;

    const int t = threadIdx.x;
    const int row0 = blockIdx.x * 64;
    const int i0 = g_idx[0], i1 = g_idx[1];

    // A load mapping: thread -> (row am, k-group akg of 8)
    const int am = t & 63, akg = t >> 6;                // akg in 0..3
    const float* aptr = x + (size_t)(row0 + am) * D_ + akg * 8;
    // B load mapping: thread -> (col bn, k-group bkg of 16)
    const int bn = t & 127, bkg = t >> 7;               // bkg in 0..1
    const float* bbase = (bn < 64) ? (We + ((size_t)i0 * L_ + bn) * D_)
                                   : (We + ((size_t)i1 * L_ + (bn - 64)) * D_);
    const float* bptr = bbase + bkg * 16;

    const int tm4 = (t >> 4) * 4;   // row micro-tile base (0..60)
    const int tn4 = (t & 15) * 4;   // col micro-tile base (0..60), second half at +64

    float c[4][8];
#pragma unroll
    for (int i = 0; i < 4; i++)
#pragma unroll
        for (int j = 0; j < 8; j++) c[i][j] = 0.f;

    // Prologue: stage chunk k0=0 in registers
    float4 pa0 = *(const float4*)(aptr);
    float4 pa1 = *(const float4*)(aptr + 4);
    float4 pb0 = *(const float4*)(bptr);
    float4 pb1 = *(const float4*)(bptr + 4);
    float4 pb2 = *(const float4*)(bptr + 8);
    float4 pb3 = *(const float4*)(bptr + 12);

    for (int k0 = 0; k0 < D_; k0 += 32) {
        // commit staged regs to smem (A transposed: As[k][m], Bs[k][n])
        {
            const int kb = akg * 8;
            sm.s.A[kb + 0][am] = pa0.x; sm.s.A[kb + 1][am] = pa0.y;
            sm.s.A[kb + 2][am] = pa0.z; sm.s.A[kb + 3][am] = pa0.w;
            sm.s.A[kb + 4][am] = pa1.x; sm.s.A[kb + 5][am] = pa1.y;
            sm.s.A[kb + 6][am] = pa1.z; sm.s.A[kb + 7][am] = pa1.w;
            const int kc = bkg * 16;
            sm.s.B[kc +  0][bn] = pb0.x; sm.s.B[kc +  1][bn] = pb0.y;
            sm.s.B[kc +  2][bn] = pb0.z; sm.s.B[kc +  3][bn] = pb0.w;
            sm.s.B[kc +  4][bn] = pb1.x; sm.s.B[kc +  5][bn] = pb1.y;
            sm.s.B[kc +  6][bn] = pb1.z; sm.s.B[kc +  7][bn] = pb1.w;
            sm.s.B[kc +  8][bn] = pb2.x; sm.s.B[kc +  9][bn] = pb2.y;
            sm.s.B[kc + 10][bn] = pb2.z; sm.s.B[kc + 11][bn] = pb2.w;
            sm.s.B[kc + 12][bn] = pb3.x; sm.s.B[kc + 13][bn] = pb3.y;
            sm.s.B[kc + 14][bn] = pb3.z; sm.s.B[kc + 15][bn] = pb3.w;
        }
        __syncthreads();

        // prefetch next chunk while computing this one
        if (k0 + 32 < D_) {
            const float* ap = aptr + k0 + 32;
            pa0 = *(const float4*)(ap);
            pa1 = *(const float4*)(ap + 4);
            const float* bp = bptr + k0 + 32;
            pb0 = *(const float4*)(bp);
            pb1 = *(const float4*)(bp + 4);
            pb2 = *(const float4*)(bp + 8);
            pb3 = *(const float4*)(bp + 12);
        }

#pragma unroll
        for (int kk = 0; kk < 32; kk++) {
            float a[4], b[8];
            *(float4*)a = *(const float4*)&sm.s.A[kk][tm4];
            *(float4*)b = *(const float4*)&sm.s.B[kk][tn4];
            *(float4*)(b + 4) = *(const float4*)&sm.s.B[kk][64 + tn4];
#pragma unroll
            for (int i = 0; i < 4; i++)
#pragma unroll
                for (int j = 0; j < 8; j++) c[i][j] = fmaf(a[i], b[j], c[i][j]);
        }
        __syncthreads();
    }

    // ---------------- epilogue: normalize per 64-wide half, GELU, combine ----
    // (union reuse: all smem reads of A/B are done — last __syncthreads covers it)
#pragma unroll
    for (int i = 0; i < 4; i++)
#pragma unroll
        for (int j = 0; j < 4; j++) {
            sm.C[tm4 + i][tn4 + j]      = c[i][j];
            sm.C[tm4 + i][64 + tn4 + j] = c[i][j + 4];
        }
    __syncthreads();

    const float g0 = g_gate[0], g1 = g_gate[1];
    const int w = t >> 5, lane = t & 31;
#pragma unroll
    for (int r = 0; r < 8; r++) {
        const int row = w * 8 + r;
        const float z0a = sm.C[row][lane];
        const float z0b = sm.C[row][lane + 32];
        const float z1a = sm.C[row][64 + lane];
        const float z1b = sm.C[row][96 + lane];
        float ss0 = z0a * z0a + z0b * z0b;
        float ss1 = z1a * z1a + z1b * z1b;
#pragma unroll
        for (int off = 16; off; off >>= 1) {
            ss0 += __shfl_xor_sync(0xffffffffu, ss0, off);
            ss1 += __shfl_xor_sync(0xffffffffu, ss1, off);
        }
        const float inv0 = 1.f / fmaxf(sqrtf(ss0), 1e-12f);
        const float inv1 = 1.f / fmaxf(sqrtf(ss1), 1e-12f);
        const float oa = g0 * gelu_exact(z0a * inv0) + g1 * gelu_exact(z1a * inv1);
        const float ob = g0 * gelu_exact(z0b * inv0) + g1 * gelu_exact(z1b * inv1);
        float* orow = out + (size_t)(row0 + row) * L_;
        orow[lane]      = oa;
        orow[lane + 32] = ob;
    }
}

// ---------------------------------------------------------------------------
extern "C" void kernel_launch(void* const* d_in, const int* in_sizes, int n_in,
                              void* d_out, int out_size) {
    const float* x      = (const float*)d_in[0];
    const float* Wg_in  = (const float*)d_in[1];
    const float* Wg_lin = (const float*)d_in[2];
    const float* Wg_out = (const float*)d_in[3];
    const float* We     = (const float*)d_in[4];
    float* out = (float*)d_out;

    k_colsum<<<NPART, 256>>>(x, Wg_out);
    k_gate<<<1, 256>>>(Wg_in, Wg_lin);
    k_expert<<<S_ / 64, 256>>>(x, We, out);
}